// round 6
// baseline (speedup 1.0000x reference)
#include <cuda_runtime.h>
#include <math.h>

// Problem constants
#define NB    16384
#define INK   64
#define CC    4
#define SP    17              // smem row stride in floats (odd -> conflict-free columns)
#define PL    272             // plane size: 16 * SP
#define TOTC  16777216LL      // NB*CC*256 complex elements in logical output

// Scratch for the intermediate M = sum_k dX[n,k]*(Ar+iAi)[k,c]  (interleaved re,im)
// 33,554,432 floats = 128 MiB. __device__ globals are the sanctioned scratch mechanism.
__device__ float g_M[2 * TOTC];

// ---------------------------------------------------------------------------
// Kernel 1: M[n,c,i,j] -> g_M. One block: 16 n-values, one channel c; 256 thr.
// ---------------------------------------------------------------------------
__global__ __launch_bounds__(256) void ax_kernel(const float* __restrict__ dX,
                                                 const float* __restrict__ Ar,
                                                 const float* __restrict__ Ai,
                                                 int nDX, int nA) {
    __shared__ float dxs[1024];                   // 16 rows x 64 k
    int tid = threadIdx.x;
    int c   = blockIdx.x & 3;
    int n0  = (blockIdx.x >> 2) << 4;

    for (int idx = tid; idx < 1024; idx += 256) {
        int g = n0 * 64 + idx;
        dxs[idx] = (g < nDX) ? dX[g] : 0.f;
    }
    __syncthreads();

    float accr[16], acci[16];
#pragma unroll
    for (int r = 0; r < 16; r++) { accr[r] = 0.f; acci[r] = 0.f; }

    for (int k = 0; k < 64; k++) {
        int gi = ((k * 4 + c) << 8) + tid;
        float ar = (gi < nA) ? Ar[gi] : 0.f;
        float ai = (gi < nA) ? Ai[gi] : 0.f;
#pragma unroll
        for (int r = 0; r < 16; r++) {
            float d = dxs[(r << 6) + k];
            accr[r] = fmaf(d, ar, accr[r]);
            acci[r] = fmaf(d, ai, acci[r]);
        }
    }
#pragma unroll
    for (int r = 0; r < 16; r++) {
        long long o = ((long long)((n0 + r) * 4 + c)) * 256 + tid;  // complex index
        g_M[2 * o]     = accr[r];
        g_M[2 * o + 1] = acci[r];
    }
}

// ---------------------------------------------------------------------------
// complex 16x16 matmul on separate re/im smem planes; thread owns row i, cols j0..j0+3
// ---------------------------------------------------------------------------
__device__ __forceinline__ void mm16(const float* Am, const float* Ax,
                                     const float* Bm, const float* Bx,
                                     float cr[4], float ci[4], int i, int j0) {
#pragma unroll
    for (int l = 0; l < 4; l++) { cr[l] = 0.f; ci[l] = 0.f; }
#pragma unroll
    for (int k = 0; k < 16; k++) {
        float ar = Am[i * SP + k];
        float ai = Ax[i * SP + k];
#pragma unroll
        for (int l = 0; l < 4; l++) {
            float br = Bm[k * SP + j0 + l];
            float bi = Bx[k * SP + j0 + l];
            cr[l] = fmaf(ar, br, fmaf(-ai, bi, cr[l]));
            ci[l] = fmaf(ar, bi, fmaf( ai, br, ci[l]));
        }
    }
}

// ---------------------------------------------------------------------------
// Kernel 2: expm of AX = 0.5*(M - M^H) via degree-15 Taylor (PS) + squaring.
// One matrix per 64-thread block. Output: real-only floats or interleaved
// complex floats depending on writeComplex; both guarded by capF (floats).
// ---------------------------------------------------------------------------
__global__ __launch_bounds__(64) void expm_kernel(float* __restrict__ out,
                                                  long long capF, int writeComplex) {
    __shared__ float sm[12 * PL];
    __shared__ float colsum[16];
    __shared__ int s_sh;

    float* Amr = sm + 0 * PL;  float* Ami = sm + 1 * PL;
    float* A2r = sm + 2 * PL;  float* A2i = sm + 3 * PL;
    float* A3r = sm + 4 * PL;  float* A3i = sm + 5 * PL;
    float* A4r = sm + 6 * PL;  float* A4i = sm + 7 * PL;
    float* Pr  = sm + 8 * PL;  float* Pi  = sm + 9 * PL;
    float* Tr  = sm + 10 * PL; float* Ti  = sm + 11 * PL;

    int t  = threadIdx.x;
    int i  = t >> 2;
    int j0 = (t & 3) << 2;

    long long baseC = (long long)blockIdx.x * 256;   // complex offset of this matrix

    // stage M into P planes (from scratch global; always in bounds)
#pragma unroll
    for (int l = 0; l < 4; l++) {
        int j = j0 + l;
        long long f = 2 * (baseC + i * 16 + j);
        Pr[i * SP + j] = g_M[f];
        Pi[i * SP + j] = g_M[f + 1];
    }
    __syncthreads();

    // AX = 0.5*(M - M^H); |AX| into Tr (as [j][i]) for induced 1-norm
    float axr[4], axi[4];
#pragma unroll
    for (int l = 0; l < 4; l++) {
        int j = j0 + l;
        axr[l] = 0.5f * (Pr[i * SP + j] - Pr[j * SP + i]);
        axi[l] = 0.5f * (Pi[i * SP + j] + Pi[j * SP + i]);
        Tr[j * 16 + i] = sqrtf(axr[l] * axr[l] + axi[l] * axi[l]);
    }
    __syncthreads();

    if (t < 16) {
        float cs = 0.f;
#pragma unroll
        for (int r = 0; r < 16; r++) cs += Tr[t * 16 + r];
        colsum[t] = cs;
    }
    __syncthreads();
    if (t == 0) {
        float m = colsum[0];
#pragma unroll
        for (int r = 1; r < 16; r++) m = fmaxf(m, colsum[r]);
        int s = 0;
        if (m > 1.0f) s = (int)ceilf(log2f(m));
        s -= 1;                       // theta = 2 for degree-15 Taylor: err ~ 3e-9
        if (s < 0) s = 0;
        if (s > 24) s = 24;
        s_sh = s;
    }
    __syncthreads();
    int s = s_sh;
    float scale = exp2f(-(float)s);
#pragma unroll
    for (int l = 0; l < 4; l++) {
        Amr[i * SP + j0 + l] = axr[l] * scale;
        Ami[i * SP + j0 + l] = axi[l] * scale;
    }
    __syncthreads();

    float r4[4], i4[4];
    mm16(Amr, Ami, Amr, Ami, r4, i4, i, j0);        // A2
#pragma unroll
    for (int l = 0; l < 4; l++) { A2r[i * SP + j0 + l] = r4[l]; A2i[i * SP + j0 + l] = i4[l]; }
    __syncthreads();
    mm16(A2r, A2i, Amr, Ami, r4, i4, i, j0);        // A3
#pragma unroll
    for (int l = 0; l < 4; l++) { A3r[i * SP + j0 + l] = r4[l]; A3i[i * SP + j0 + l] = i4[l]; }
    mm16(A2r, A2i, A2r, A2i, r4, i4, i, j0);        // A4
#pragma unroll
    for (int l = 0; l < 4; l++) { A4r[i * SP + j0 + l] = r4[l]; A4i[i * SP + j0 + l] = i4[l]; }
    __syncthreads();

    const float c2  = 0.5f;
    const float c3  = 1.6666666666666666e-01f;
    const float c4  = 4.1666666666666664e-02f;
    const float c5  = 8.3333333333333332e-03f;
    const float c6  = 1.3888888888888889e-03f;
    const float c7  = 1.9841269841269841e-04f;
    const float c8  = 2.4801587301587302e-05f;
    const float c9  = 2.7557319223985893e-06f;
    const float c10 = 2.7557319223985888e-07f;
    const float c11 = 2.5052108385441720e-08f;
    const float c12 = 2.0876756987868100e-09f;
    const float c13 = 1.6059043836821613e-10f;
    const float c14 = 1.1470745597729725e-11f;
    const float c15 = 7.6471637318198164e-13f;

    // P = c12 I + c13 A + c14 A2 + c15 A3
#pragma unroll
    for (int l = 0; l < 4; l++) {
        int e = i * SP + j0 + l;
        float vr = c13 * Amr[e] + c14 * A2r[e] + c15 * A3r[e];
        float vi = c13 * Ami[e] + c14 * A2i[e] + c15 * A3i[e];
        if (i == j0 + l) vr += c12;
        Pr[e] = vr; Pi[e] = vi;
    }
    __syncthreads();

    float* pr = Pr; float* pi = Pi;
    float* tr = Tr; float* ti = Ti;

    const float h0[3] = { c8, c4, 1.0f };
    const float h1[3] = { c9, c5, 1.0f };
    const float h2[3] = { c10, c6, c2 };
    const float h3[3] = { c11, c7, c3 };
#pragma unroll
    for (int stp = 0; stp < 3; stp++) {
        mm16(pr, pi, A4r, A4i, r4, i4, i, j0);
#pragma unroll
        for (int l = 0; l < 4; l++) {
            int e = i * SP + j0 + l;
            float vr = r4[l] + h1[stp] * Amr[e] + h2[stp] * A2r[e] + h3[stp] * A3r[e];
            float vi = i4[l] + h1[stp] * Ami[e] + h2[stp] * A2i[e] + h3[stp] * A3i[e];
            if (i == j0 + l) vr += h0[stp];
            tr[e] = vr; ti[e] = vi;
        }
        __syncthreads();
        float* sw;
        sw = pr; pr = tr; tr = sw;
        sw = pi; pi = ti; ti = sw;
    }

    for (int it = 0; it < s; it++) {
        mm16(pr, pi, pr, pi, r4, i4, i, j0);
#pragma unroll
        for (int l = 0; l < 4; l++) {
            int e = i * SP + j0 + l;
            tr[e] = r4[l]; ti[e] = i4[l];
        }
        __syncthreads();
        float* sw;
        sw = pr; pr = tr; tr = sw;
        sw = pi; pi = ti; ti = sw;
    }

    // write result, format per harness convention
    if (writeComplex) {
#pragma unroll
        for (int l = 0; l < 4; l++) {
            int j = j0 + l;
            long long f = 2 * (baseC + i * 16 + j);
            if (f + 1 < capF) { out[f] = pr[i * SP + j]; out[f + 1] = pi[i * SP + j]; }
        }
    } else {
#pragma unroll
        for (int l = 0; l < 4; l++) {
            int j = j0 + l;
            long long e = baseC + i * 16 + j;
            if (e < capF) out[e] = pr[i * SP + j];
        }
    }
}

// ---------------------------------------------------------------------------
extern "C" void kernel_launch(void* const* d_in, const int* in_sizes, int n_in,
                              void* d_out, int out_size) {
    // dX is the input with N*IN elements (accept element or byte counts);
    // remaining two inputs are Ar, Ai in original order.
    int ix_dX = -1;
    for (int i = 0; i < n_in; i++)
        if (in_sizes[i] == (int)(NB * INK) || in_sizes[i] == (int)(NB * INK * 4)) { ix_dX = i; break; }
    if (ix_dX < 0) ix_dX = 0;
    int ia[2] = {0, 0}; int na = 0;
    for (int i = 0; i < n_in && na < 2; i++)
        if (i != ix_dX) ia[na++] = i;

    const float* dX = (const float*)d_in[ix_dX];
    const float* Ar = (const float*)d_in[ia[0]];
    const float* Ai = (const float*)d_in[ia[1]];
    float* outf = (float*)d_out;

    int nDX = in_sizes[ix_dX];
    int nA  = in_sizes[ia[0]] < in_sizes[ia[1]] ? in_sizes[ia[0]] : in_sizes[ia[1]];

    // Conservative capacity: assume the buffer holds out_size FLOATS (the smallest
    // consistent interpretation). Clamp to the logical maximum of 2*TOTC floats.
    long long capF = (long long)out_size;
    if (capF > 2LL * TOTC) capF = 2LL * TOTC;
    // If out_size is large enough for the full interleaved complex view, write
    // re/im pairs; otherwise write real parts only (astype(float32) convention).
    int writeComplex = (capF >= 2LL * TOTC) ? 1 : 0;

    ax_kernel<<<(NB / 16) * CC, 256>>>(dX, Ar, Ai, nDX, nA);   // 4096 blocks
    expm_kernel<<<NB * CC, 64>>>(outf, capF, writeComplex);    // 65536 blocks
}

// round 7
// speedup vs baseline: 1.2638x; 1.2638x over previous
#include <cuda_runtime.h>
#include <math.h>

// Problem constants
#define NB    16384
#define INK   64
#define CC    4
#define SPC   18              // smem row stride in float2 units (even -> 16B-aligned rows, conflict-free)
#define PL    288             // plane size: 16 * SPC (float2)
#define TOTC  16777216LL      // NB*CC*256 complex elements in logical output

// Scratch for intermediate M = sum_k dX[n,k]*(Ar+iAi)[k,c]  (interleaved re,im), 128 MiB
__device__ float2 g_M[TOTC];

// ---------------------------------------------------------------------------
// Kernel 1: M[n,c,i,j] -> g_M. One block: 16 n-values, one channel c; 256 thr.
// ---------------------------------------------------------------------------
__global__ __launch_bounds__(256) void ax_kernel(const float* __restrict__ dX,
                                                 const float* __restrict__ Ar,
                                                 const float* __restrict__ Ai,
                                                 int nDX, int nA) {
    __shared__ float dxs[1024];                   // 16 rows x 64 k
    int tid = threadIdx.x;
    int c   = blockIdx.x & 3;
    int n0  = (blockIdx.x >> 2) << 4;

    for (int idx = tid; idx < 1024; idx += 256) {
        int g = n0 * 64 + idx;
        dxs[idx] = (g < nDX) ? dX[g] : 0.f;
    }
    __syncthreads();

    float accr[16], acci[16];
#pragma unroll
    for (int r = 0; r < 16; r++) { accr[r] = 0.f; acci[r] = 0.f; }

    for (int k = 0; k < 64; k++) {
        int gi = ((k * 4 + c) << 8) + tid;
        float ar = (gi < nA) ? Ar[gi] : 0.f;
        float ai = (gi < nA) ? Ai[gi] : 0.f;
#pragma unroll
        for (int r = 0; r < 16; r++) {
            float d = dxs[(r << 6) + k];
            accr[r] = fmaf(d, ar, accr[r]);
            acci[r] = fmaf(d, ai, acci[r]);
        }
    }
#pragma unroll
    for (int r = 0; r < 16; r++) {
        long long o = ((long long)((n0 + r) * 4 + c)) * 256 + tid;  // complex index
        g_M[o] = make_float2(accr[r], acci[r]);
    }
}

// ---------------------------------------------------------------------------
// Packed f32x2 helpers
// ---------------------------------------------------------------------------
__device__ __forceinline__ unsigned long long pk2(float lo, float hi) {
    unsigned long long r;
    asm("mov.b64 %0, {%1, %2};" : "=l"(r) : "f"(lo), "f"(hi));
    return r;
}
__device__ __forceinline__ void upk2(unsigned long long v, float& lo, float& hi) {
    asm("mov.b64 {%0, %1}, %2;" : "=f"(lo), "=f"(hi) : "l"(v));
}
__device__ __forceinline__ unsigned long long ffma2(unsigned long long a,
                                                    unsigned long long b,
                                                    unsigned long long c) {
    unsigned long long r;
    asm("fma.rn.f32x2 %0, %1, %2, %3;" : "=l"(r) : "l"(a), "l"(b), "l"(c));
    return r;
}

// ---------------------------------------------------------------------------
// complex 16x16 matmul, interleaved float2 planes, packed-FFMA2 inner loop.
// Thread owns row i, cols j0..j0+3. Dual accumulators avoid per-k swaps:
//   accP[l] += (ar,ar)*(br,bi),  accQ[l] += (ai,ai)*(br,bi)
//   cr = accP.lo - accQ.hi,  ci = accP.hi + accQ.lo
// ---------------------------------------------------------------------------
__device__ __forceinline__ void mm16(const float2* __restrict__ A,
                                     const float2* __restrict__ B,
                                     float2 c[4], int i, int j0) {
    unsigned long long accP[4], accQ[4];
#pragma unroll
    for (int l = 0; l < 4; l++) { accP[l] = 0ULL; accQ[l] = 0ULL; }
#pragma unroll
    for (int k = 0; k < 16; k++) {
        float2 a = A[i * SPC + k];
        unsigned long long arr = pk2(a.x, a.x);
        unsigned long long aii = pk2(a.y, a.y);
        ulonglong2 b01 = *(const ulonglong2*)(B + k * SPC + j0);
        ulonglong2 b23 = *(const ulonglong2*)(B + k * SPC + j0 + 2);
        accP[0] = ffma2(arr, b01.x, accP[0]);  accQ[0] = ffma2(aii, b01.x, accQ[0]);
        accP[1] = ffma2(arr, b01.y, accP[1]);  accQ[1] = ffma2(aii, b01.y, accQ[1]);
        accP[2] = ffma2(arr, b23.x, accP[2]);  accQ[2] = ffma2(aii, b23.x, accQ[2]);
        accP[3] = ffma2(arr, b23.y, accP[3]);  accQ[3] = ffma2(aii, b23.y, accQ[3]);
    }
#pragma unroll
    for (int l = 0; l < 4; l++) {
        float pr, pi2, qr, qi;
        upk2(accP[l], pr, pi2);
        upk2(accQ[l], qr, qi);
        c[l] = make_float2(pr - qi, pi2 + qr);
    }
}

__device__ __forceinline__ void store4(float2* __restrict__ dst,
                                       const float2 c[4], int i, int j0) {
    float4* p = (float4*)(dst + i * SPC + j0);
    p[0] = make_float4(c[0].x, c[0].y, c[1].x, c[1].y);
    p[1] = make_float4(c[2].x, c[2].y, c[3].x, c[3].y);
}

// ---------------------------------------------------------------------------
// Kernel 2: expm of AX = 0.5*(M - M^H), degree-15 Taylor (PS) + squaring.
// One matrix per 64-thread block; thread t: row i = t>>2, cols j0=(t&3)*4..+3.
// ---------------------------------------------------------------------------
__global__ __launch_bounds__(64) void expm_kernel(float* __restrict__ out,
                                                  long long capF, int writeComplex) {
    __shared__ __align__(16) float2 sm[6 * PL];
    __shared__ float colsum[16];
    __shared__ int s_sh;

    float2* Am = sm + 0 * PL;
    float2* A2 = sm + 1 * PL;
    float2* A3 = sm + 2 * PL;
    float2* A4 = sm + 3 * PL;
    float2* Pp = sm + 4 * PL;
    float2* Tp = sm + 5 * PL;

    int t  = threadIdx.x;
    int i  = t >> 2;
    int j0 = (t & 3) << 2;

    long long baseC = (long long)blockIdx.x * 256;   // complex offset of this matrix

    // stage M into P plane (vectorized: 2x float4)
    {
        const float4* gm = (const float4*)(g_M + baseC + i * 16 + j0);
        float4 v0 = gm[0], v1 = gm[1];
        float4* p = (float4*)(Pp + i * SPC + j0);
        p[0] = v0; p[1] = v1;
    }
    __syncthreads();

    // AX = 0.5*(M - M^H); |AX| into fb[j*16+i] for induced 1-norm
    float* fb = (float*)Tp;
    float axr[4], axi[4];
#pragma unroll
    for (int l = 0; l < 4; l++) {
        int j = j0 + l;
        float2 mij = Pp[i * SPC + j];
        float2 mji = Pp[j * SPC + i];
        axr[l] = 0.5f * (mij.x - mji.x);
        axi[l] = 0.5f * (mij.y + mji.y);
        fb[j * 16 + i] = sqrtf(axr[l] * axr[l] + axi[l] * axi[l]);
    }
    __syncthreads();

    if (t < 16) {
        float cs = 0.f;
#pragma unroll
        for (int r = 0; r < 16; r++) cs += fb[t * 16 + r];
        colsum[t] = cs;
    }
    __syncthreads();
    if (t == 0) {
        float m = colsum[0];
#pragma unroll
        for (int r = 1; r < 16; r++) m = fmaxf(m, colsum[r]);
        int s = 0;
        if (m > 1.0f) s = (int)ceilf(log2f(m));
        s -= 1;                       // theta = 2 for degree-15 Taylor: err ~ 3e-9
        if (s < 0) s = 0;
        if (s > 24) s = 24;
        s_sh = s;
    }
    __syncthreads();
    int s = s_sh;
    float scale = exp2f(-(float)s);
    {
        float2 c[4];
#pragma unroll
        for (int l = 0; l < 4; l++) c[l] = make_float2(axr[l] * scale, axi[l] * scale);
        store4(Am, c, i, j0);
    }
    __syncthreads();

    float2 c[4];
    mm16(Am, Am, c, i, j0); store4(A2, c, i, j0);        // A2
    __syncthreads();
    mm16(A2, Am, c, i, j0); store4(A3, c, i, j0);        // A3
    mm16(A2, A2, c, i, j0); store4(A4, c, i, j0);        // A4
    __syncthreads();

    const float c2  = 0.5f;
    const float c3  = 1.6666666666666666e-01f;
    const float c4  = 4.1666666666666664e-02f;
    const float c5  = 8.3333333333333332e-03f;
    const float c6  = 1.3888888888888889e-03f;
    const float c7  = 1.9841269841269841e-04f;
    const float c8  = 2.4801587301587302e-05f;
    const float c9  = 2.7557319223985893e-06f;
    const float c10 = 2.7557319223985888e-07f;
    const float c11 = 2.5052108385441720e-08f;
    const float c12 = 2.0876756987868100e-09f;
    const float c13 = 1.6059043836821613e-10f;
    const float c14 = 1.1470745597729725e-11f;
    const float c15 = 7.6471637318198164e-13f;

    // P = c12 I + c13 A + c14 A2 + c15 A3
#pragma unroll
    for (int l = 0; l < 4; l++) {
        int e = i * SPC + j0 + l;
        float2 a = Am[e], b2 = A2[e], b3 = A3[e];
        float2 v;
        v.x = c13 * a.x + c14 * b2.x + c15 * b3.x;
        v.y = c13 * a.y + c14 * b2.y + c15 * b3.y;
        if (i == j0 + l) v.x += c12;
        Pp[e] = v;
    }
    __syncthreads();

    float2* pr = Pp;
    float2* tr = Tp;

    const float h0[3] = { c8, c4, 1.0f };
    const float h1[3] = { c9, c5, 1.0f };
    const float h2[3] = { c10, c6, c2 };
    const float h3[3] = { c11, c7, c3 };
#pragma unroll
    for (int stp = 0; stp < 3; stp++) {
        mm16(pr, A4, c, i, j0);
#pragma unroll
        for (int l = 0; l < 4; l++) {
            int e = i * SPC + j0 + l;
            float2 a = Am[e], b2 = A2[e], b3 = A3[e];
            float2 v = c[l];
            v.x += h1[stp] * a.x + h2[stp] * b2.x + h3[stp] * b3.x;
            v.y += h1[stp] * a.y + h2[stp] * b2.y + h3[stp] * b3.y;
            if (i == j0 + l) v.x += h0[stp];
            tr[e] = v;
        }
        __syncthreads();
        float2* sw = pr; pr = tr; tr = sw;
    }

    // repeated squaring (uniform per block)
    for (int it = 0; it < s; it++) {
        mm16(pr, pr, c, i, j0);
        store4(tr, c, i, j0);
        __syncthreads();
        float2* sw = pr; pr = tr; tr = sw;
    }

    // write result per harness convention (real-only float32 confirmed)
    if (writeComplex) {
#pragma unroll
        for (int l = 0; l < 4; l++) {
            int j = j0 + l;
            long long f = 2 * (baseC + i * 16 + j);
            float2 v = pr[i * SPC + j];
            if (f + 1 < capF) { out[f] = v.x; out[f + 1] = v.y; }
        }
    } else {
        long long e = baseC + i * 16 + j0;
        if (e + 3 < capF) {
            float2 v0 = pr[i * SPC + j0],     v1 = pr[i * SPC + j0 + 1];
            float2 v2 = pr[i * SPC + j0 + 2], v3 = pr[i * SPC + j0 + 3];
            *(float4*)(out + e) = make_float4(v0.x, v1.x, v2.x, v3.x);
        }
    }
}

// ---------------------------------------------------------------------------
extern "C" void kernel_launch(void* const* d_in, const int* in_sizes, int n_in,
                              void* d_out, int out_size) {
    int ix_dX = -1;
    for (int i = 0; i < n_in; i++)
        if (in_sizes[i] == (int)(NB * INK) || in_sizes[i] == (int)(NB * INK * 4)) { ix_dX = i; break; }
    if (ix_dX < 0) ix_dX = 0;
    int ia[2] = {0, 0}; int na = 0;
    for (int i = 0; i < n_in && na < 2; i++)
        if (i != ix_dX) ia[na++] = i;

    const float* dX = (const float*)d_in[ix_dX];
    const float* Ar = (const float*)d_in[ia[0]];
    const float* Ai = (const float*)d_in[ia[1]];
    float* outf = (float*)d_out;

    int nDX = in_sizes[ix_dX];
    int nA  = in_sizes[ia[0]] < in_sizes[ia[1]] ? in_sizes[ia[0]] : in_sizes[ia[1]];

    long long capF = (long long)out_size;
    if (capF > 2LL * TOTC) capF = 2LL * TOTC;
    int writeComplex = (capF >= 2LL * TOTC) ? 1 : 0;

    ax_kernel<<<(NB / 16) * CC, 256>>>(dX, Ar, Ai, nDX, nA);   // 4096 blocks
    expm_kernel<<<NB * CC, 64>>>(outf, capF, writeComplex);    // 65536 blocks
}

// round 9
// speedup vs baseline: 1.8160x; 1.4369x over previous
#include <cuda_runtime.h>
#include <math.h>

// Problem constants
#define NB    16384
#define INK   64
#define CC    4
#define SPC   18              // smem row stride in float2 (even -> 16B-aligned rows; A-col loads 2-way max)
#define PL    288             // plane size: 16 * SPC (float2)
#define MPB   4               // matrices (warps) per block
#define TOTC  16777216LL      // NB*CC*256 complex elements

// Scratch for intermediate M = sum_k dX[n,k]*(Ar+iAi)[k,c]  (interleaved re,im), 128 MiB
__device__ float2 g_M[TOTC];

// ---------------------------------------------------------------------------
// Kernel 1: M[n,c,i,j] -> g_M. One block: 16 n-values, one channel c; 256 thr.
// ---------------------------------------------------------------------------
__global__ __launch_bounds__(256) void ax_kernel(const float* __restrict__ dX,
                                                 const float* __restrict__ Ar,
                                                 const float* __restrict__ Ai,
                                                 int nDX, int nA) {
    __shared__ float dxs[1024];                   // 16 rows x 64 k
    int tid = threadIdx.x;
    int c   = blockIdx.x & 3;
    int n0  = (blockIdx.x >> 2) << 4;

    for (int idx = tid; idx < 1024; idx += 256) {
        int g = n0 * 64 + idx;
        dxs[idx] = (g < nDX) ? dX[g] : 0.f;
    }
    __syncthreads();

    float accr[16], acci[16];
#pragma unroll
    for (int r = 0; r < 16; r++) { accr[r] = 0.f; acci[r] = 0.f; }

    for (int k = 0; k < 64; k++) {
        int gi = ((k * 4 + c) << 8) + tid;
        float ar = (gi < nA) ? Ar[gi] : 0.f;
        float ai = (gi < nA) ? Ai[gi] : 0.f;
#pragma unroll
        for (int r = 0; r < 16; r++) {
            float d = dxs[(r << 6) + k];
            accr[r] = fmaf(d, ar, accr[r]);
            acci[r] = fmaf(d, ai, acci[r]);
        }
    }
#pragma unroll
    for (int r = 0; r < 16; r++) {
        long long o = ((long long)((n0 + r) * 4 + c)) * 256 + tid;
        g_M[o] = make_float2(accr[r], acci[r]);
    }
}

// ---------------------------------------------------------------------------
// Packed f32x2 helpers
// ---------------------------------------------------------------------------
__device__ __forceinline__ unsigned long long pk2(float lo, float hi) {
    unsigned long long r;
    asm("mov.b64 %0, {%1, %2};" : "=l"(r) : "f"(lo), "f"(hi));
    return r;
}
__device__ __forceinline__ void upk2(unsigned long long v, float& lo, float& hi) {
    asm("mov.b64 {%0, %1}, %2;" : "=f"(lo), "=f"(hi) : "l"(v));
}
__device__ __forceinline__ unsigned long long ffma2(unsigned long long a,
                                                    unsigned long long b,
                                                    unsigned long long c) {
    unsigned long long r;
    asm("fma.rn.f32x2 %0, %1, %2, %3;" : "=l"(r) : "l"(a), "l"(b), "l"(c));
    return r;
}

// ---------------------------------------------------------------------------
// complex 16x16 matmul, 2x4 per-thread tile: rows i0,i0+1, cols j0..j0+3.
// Dual packed accumulators: cr = P.lo - Q.hi, ci = P.hi + Q.lo.
// ---------------------------------------------------------------------------
__device__ __forceinline__ void mm16_24(const float2* __restrict__ A,
                                        const float2* __restrict__ B,
                                        float2 c[2][4], int i0, int j0) {
    unsigned long long accP[2][4], accQ[2][4];
#pragma unroll
    for (int r = 0; r < 2; r++)
#pragma unroll
        for (int l = 0; l < 4; l++) { accP[r][l] = 0ULL; accQ[r][l] = 0ULL; }
#pragma unroll
    for (int k = 0; k < 16; k++) {
        float2 a0 = A[i0 * SPC + k];
        float2 a1 = A[(i0 + 1) * SPC + k];
        unsigned long long a0r = pk2(a0.x, a0.x);
        unsigned long long a0i = pk2(a0.y, a0.y);
        unsigned long long a1r = pk2(a1.x, a1.x);
        unsigned long long a1i = pk2(a1.y, a1.y);
        ulonglong2 b01 = *(const ulonglong2*)(B + k * SPC + j0);
        ulonglong2 b23 = *(const ulonglong2*)(B + k * SPC + j0 + 2);
        accP[0][0] = ffma2(a0r, b01.x, accP[0][0]);  accQ[0][0] = ffma2(a0i, b01.x, accQ[0][0]);
        accP[0][1] = ffma2(a0r, b01.y, accP[0][1]);  accQ[0][1] = ffma2(a0i, b01.y, accQ[0][1]);
        accP[0][2] = ffma2(a0r, b23.x, accP[0][2]);  accQ[0][2] = ffma2(a0i, b23.x, accQ[0][2]);
        accP[0][3] = ffma2(a0r, b23.y, accP[0][3]);  accQ[0][3] = ffma2(a0i, b23.y, accQ[0][3]);
        accP[1][0] = ffma2(a1r, b01.x, accP[1][0]);  accQ[1][0] = ffma2(a1i, b01.x, accQ[1][0]);
        accP[1][1] = ffma2(a1r, b01.y, accP[1][1]);  accQ[1][1] = ffma2(a1i, b01.y, accQ[1][1]);
        accP[1][2] = ffma2(a1r, b23.x, accP[1][2]);  accQ[1][2] = ffma2(a1i, b23.x, accQ[1][2]);
        accP[1][3] = ffma2(a1r, b23.y, accP[1][3]);  accQ[1][3] = ffma2(a1i, b23.y, accQ[1][3]);
    }
#pragma unroll
    for (int r = 0; r < 2; r++)
#pragma unroll
        for (int l = 0; l < 4; l++) {
            float pr, pi2, qr, qi;
            upk2(accP[r][l], pr, pi2);
            upk2(accQ[r][l], qr, qi);
            c[r][l] = make_float2(pr - qi, pi2 + qr);
        }
}

__device__ __forceinline__ void store24(float2* __restrict__ dst,
                                        const float2 c[2][4], int i0, int j0) {
#pragma unroll
    for (int r = 0; r < 2; r++) {
        float4* p = (float4*)(dst + (i0 + r) * SPC + j0);
        p[0] = make_float4(c[r][0].x, c[r][0].y, c[r][1].x, c[r][1].y);
        p[1] = make_float4(c[r][2].x, c[r][2].y, c[r][3].x, c[r][3].y);
    }
}

// ---------------------------------------------------------------------------
// Kernel 2: expm of AX = 0.5*(M - M^H), degree-15 Taylor (PS) + squaring.
// ONE WARP PER MATRIX; 4 matrices per 128-thread block. Thread lane t:
// row-pair rp = t>>2 (rows 2rp, 2rp+1), col-group cg = t&3 (cols 4cg..4cg+3).
// Planes per matrix: A, A2, A3, A4, P (squaring ping-pongs P <-> A).
// ---------------------------------------------------------------------------
__global__ __launch_bounds__(128) void expm_kernel(float* __restrict__ out,
                                                   long long capF, int writeComplex) {
    __shared__ __align__(16) float2 sm[MPB][5 * PL];

    int lane = threadIdx.x & 31;
    int w    = threadIdx.x >> 5;
    int i0   = (lane >> 2) << 1;
    int j0   = (lane & 3) << 2;

    float2* Am = sm[w];
    float2* A2 = Am + PL;
    float2* A3 = Am + 2 * PL;
    float2* A4 = Am + 3 * PL;
    float2* Pp = Am + 4 * PL;

    long long baseC = ((long long)blockIdx.x * MPB + w) * 256;

    // stage M tile (own 2 rows x 4 cols) into P plane
    {
        const float4* g0 = (const float4*)(g_M + baseC + i0 * 16 + j0);
        const float4* g1 = (const float4*)(g_M + baseC + (i0 + 1) * 16 + j0);
        float4 v00 = g0[0], v01 = g0[1], v10 = g1[0], v11 = g1[1];
        float4* p0 = (float4*)(Pp + i0 * SPC + j0);
        float4* p1 = (float4*)(Pp + (i0 + 1) * SPC + j0);
        p0[0] = v00; p0[1] = v01; p1[0] = v10; p1[1] = v11;
    }
    __syncwarp();

    // AX = 0.5*(M - M^H) for own tile; per-column partial abs-sums
    float2 ax[2][4];
    float cs[4];
#pragma unroll
    for (int l = 0; l < 4; l++) cs[l] = 0.f;
#pragma unroll
    for (int r = 0; r < 2; r++) {
        int i = i0 + r;
#pragma unroll
        for (int l = 0; l < 4; l++) {
            int j = j0 + l;
            float2 mij = Pp[i * SPC + j];
            float2 mji = Pp[j * SPC + i];
            float xr = 0.5f * (mij.x - mji.x);
            float xi = 0.5f * (mij.y + mji.y);
            ax[r][l] = make_float2(xr, xi);
            cs[l] += sqrtf(xr * xr + xi * xi);
        }
    }
    // reduce column sums over row-pairs (lanes differing in bits 2..4)
#pragma unroll
    for (int off = 16; off >= 4; off >>= 1) {
#pragma unroll
        for (int l = 0; l < 4; l++)
            cs[l] += __shfl_xor_sync(0xffffffffu, cs[l], off);
    }
    float mx = fmaxf(fmaxf(cs[0], cs[1]), fmaxf(cs[2], cs[3]));
#pragma unroll
    for (int off = 2; off >= 1; off >>= 1)
        mx = fmaxf(mx, __shfl_xor_sync(0xffffffffu, mx, off));

    int s = 0;
    if (mx > 1.0f) s = (int)ceilf(log2f(mx));
    s -= 1;                     // theta = 2 for degree-15 Taylor: trunc ~ 3e-9
    if (s < 0) s = 0;
    if (s > 24) s = 24;
    float scale = exp2f(-(float)s);

    // write scaled A
    {
        float2 c[2][4];
#pragma unroll
        for (int r = 0; r < 2; r++)
#pragma unroll
            for (int l = 0; l < 4; l++)
                c[r][l] = make_float2(ax[r][l].x * scale, ax[r][l].y * scale);
        store24(Am, c, i0, j0);
    }
    __syncwarp();

    float2 c[2][4];
    mm16_24(Am, Am, c, i0, j0); store24(A2, c, i0, j0);      // A2
    __syncwarp();
    mm16_24(A2, Am, c, i0, j0); store24(A3, c, i0, j0);      // A3 (only read element-wise)
    mm16_24(A2, A2, c, i0, j0); store24(A4, c, i0, j0);      // A4 (read as B in Horner)
    __syncwarp();

    const float c2  = 0.5f;
    const float c3  = 1.6666666666666666e-01f;
    const float c4  = 4.1666666666666664e-02f;
    const float c5  = 8.3333333333333332e-03f;
    const float c6  = 1.3888888888888889e-03f;
    const float c7  = 1.9841269841269841e-04f;
    const float c8  = 2.4801587301587302e-05f;
    const float c9  = 2.7557319223985893e-06f;
    const float c10 = 2.7557319223985888e-07f;
    const float c11 = 2.5052108385441720e-08f;
    const float c12 = 2.0876756987868100e-09f;
    const float c13 = 1.6059043836821613e-10f;
    const float c14 = 1.1470745597729725e-11f;
    const float c15 = 7.6471637318198164e-13f;

    // P = c12 I + c13 A + c14 A2 + c15 A3  (own rows)
#pragma unroll
    for (int r = 0; r < 2; r++) {
        int i = i0 + r;
#pragma unroll
        for (int l = 0; l < 4; l++) {
            int e = i * SPC + j0 + l;
            float2 a = Am[e], b2 = A2[e], b3 = A3[e];
            float2 v;
            v.x = c13 * a.x + c14 * b2.x + c15 * b3.x;
            v.y = c13 * a.y + c14 * b2.y + c15 * b3.y;
            if (i == j0 + l) v.x += c12;
            Pp[e] = v;
        }
    }
    __syncwarp();

    // Horner x3: P = P*A4 + (h0 I + h1 A + h2 A2 + h3 A3)
    // In-place: B-operand is static A4 and each thread touches only its own rows
    // of P -> NO synchronization needed between steps.
    const float h0[3] = { c8, c4, 1.0f };
    const float h1[3] = { c9, c5, 1.0f };
    const float h2[3] = { c10, c6, c2 };
    const float h3[3] = { c11, c7, c3 };
#pragma unroll
    for (int stp = 0; stp < 3; stp++) {
        mm16_24(Pp, A4, c, i0, j0);
#pragma unroll
        for (int r = 0; r < 2; r++) {
            int i = i0 + r;
#pragma unroll
            for (int l = 0; l < 4; l++) {
                int e = i * SPC + j0 + l;
                float2 a = Am[e], b2 = A2[e], b3 = A3[e];
                float2 v = c[r][l];
                v.x += h1[stp] * a.x + h2[stp] * b2.x + h3[stp] * b3.x;
                v.y += h1[stp] * a.y + h2[stp] * b2.y + h3[stp] * b3.y;
                if (i == j0 + l) v.x += h0[stp];
                Pp[e] = v;
            }
        }
    }
    __syncwarp();

    // repeated squaring: ping-pong P <-> A plane (A..A4 are dead now)
    float2* pr = Pp;
    float2* tr = Am;
    for (int it = 0; it < s; it++) {
        mm16_24(pr, pr, c, i0, j0);
        store24(tr, c, i0, j0);
        __syncwarp();
        float2* sw = pr; pr = tr; tr = sw;
    }

    // write result (real-only float32 confirmed; complex path kept as fallback)
    if (writeComplex) {
#pragma unroll
        for (int r = 0; r < 2; r++) {
            int i = i0 + r;
#pragma unroll
            for (int l = 0; l < 4; l++) {
                int j = j0 + l;
                long long f = 2 * (baseC + i * 16 + j);
                float2 v = pr[i * SPC + j];
                if (f + 1 < capF) { out[f] = v.x; out[f + 1] = v.y; }
            }
        }
    } else {
#pragma unroll
        for (int r = 0; r < 2; r++) {
            int i = i0 + r;
            long long e = baseC + i * 16 + j0;
            if (e + 3 < capF) {
                float2 v0 = pr[i * SPC + j0],     v1 = pr[i * SPC + j0 + 1];
                float2 v2 = pr[i * SPC + j0 + 2], v3 = pr[i * SPC + j0 + 3];
                *(float4*)(out + e) = make_float4(v0.x, v1.x, v2.x, v3.x);
            }
        }
    }
}

// ---------------------------------------------------------------------------
extern "C" void kernel_launch(void* const* d_in, const int* in_sizes, int n_in,
                              void* d_out, int out_size) {
    int ix_dX = -1;
    for (int i = 0; i < n_in; i++)
        if (in_sizes[i] == (int)(NB * INK) || in_sizes[i] == (int)(NB * INK * 4)) { ix_dX = i; break; }
    if (ix_dX < 0) ix_dX = 0;
    int ia[2] = {0, 0}; int na = 0;
    for (int i = 0; i < n_in && na < 2; i++)
        if (i != ix_dX) ia[na++] = i;

    const float* dX = (const float*)d_in[ix_dX];
    const float* Ar = (const float*)d_in[ia[0]];
    const float* Ai = (const float*)d_in[ia[1]];
    float* outf = (float*)d_out;

    int nDX = in_sizes[ix_dX];
    int nA  = in_sizes[ia[0]] < in_sizes[ia[1]] ? in_sizes[ia[0]] : in_sizes[ia[1]];

    long long capF = (long long)out_size;
    if (capF > 2LL * TOTC) capF = 2LL * TOTC;
    int writeComplex = (capF >= 2LL * TOTC) ? 1 : 0;

    ax_kernel<<<(NB / 16) * CC, 256>>>(dX, Ar, Ai, nDX, nA);     // 4096 blocks
    expm_kernel<<<NB * CC / MPB, 32 * MPB>>>(outf, capF, writeComplex);  // 16384 blocks
}

// round 11
// speedup vs baseline: 1.8825x; 1.0366x over previous
#include <cuda_runtime.h>
#include <math.h>

// Problem constants
#define NB    16384
#define INK   64
#define CC    4
#define TOTC  16777216LL      // NB*CC*256 complex elements

// smem layout (float2 units): addr(i,j) = (i>>2)*68 + (i&3)*16 + j
// group stride 68 == 4 (mod 16)  -> A-column LDS.64 conflict-free
// matrix stride 1090 == 2 (mod 16) -> the two matrices of a warp interleave banks
#define GST   68
#define PL2   272             // plane: 4 groups * 68
#define MST   1090            // 4 planes * 272 + 2
#define MPB   4               // matrices per 64-thread block (2 per warp)
#define EIDX(i,j) ((((i) >> 2) * GST) + (((i) & 3) << 4) + (j))

// Scratch for intermediate M (interleaved re,im), 128 MiB
__device__ float2 g_M[TOTC];

// ---------------------------------------------------------------------------
// Packed f32x2 helpers
// ---------------------------------------------------------------------------
__device__ __forceinline__ unsigned long long pk2(float lo, float hi) {
    unsigned long long r;
    asm("mov.b64 %0, {%1, %2};" : "=l"(r) : "f"(lo), "f"(hi));
    return r;
}
__device__ __forceinline__ void upk2(unsigned long long v, float& lo, float& hi) {
    asm("mov.b64 {%0, %1}, %2;" : "=f"(lo), "=f"(hi) : "l"(v));
}
__device__ __forceinline__ unsigned long long ffma2(unsigned long long a,
                                                    unsigned long long b,
                                                    unsigned long long c) {
    unsigned long long r;
    asm("fma.rn.f32x2 %0, %1, %2, %3;" : "=l"(r) : "l"(a), "l"(b), "l"(c));
    return r;
}

// ---------------------------------------------------------------------------
// Kernel 1: M[n,c,i,j] -> g_M. One block: 16 n-values, one channel c; 256 thr.
// dX staged duplicated as (d,d) float2 so the inner loop is pure FFMA2.
// ---------------------------------------------------------------------------
__global__ __launch_bounds__(256) void ax_kernel(const float* __restrict__ dX,
                                                 const float* __restrict__ Ar,
                                                 const float* __restrict__ Ai,
                                                 int nDX, int nA) {
    __shared__ __align__(16) float2 dxs2[16][64];   // 8 KB, (d,d) duplicated
    int tid = threadIdx.x;
    int c   = blockIdx.x & 3;
    int n0  = (blockIdx.x >> 2) << 4;

    for (int idx = tid; idx < 1024; idx += 256) {
        int g = n0 * 64 + idx;
        float d = (g < nDX) ? dX[g] : 0.f;
        dxs2[idx >> 6][idx & 63] = make_float2(d, d);
    }
    __syncthreads();

    unsigned long long acc[16];
#pragma unroll
    for (int r = 0; r < 16; r++) acc[r] = 0ULL;

#pragma unroll 4
    for (int k = 0; k < 64; k += 2) {
        int gi0 = (((k    ) * 4 + c) << 8) + tid;
        int gi1 = (((k + 1) * 4 + c) << 8) + tid;
        float ar0 = (gi0 < nA) ? Ar[gi0] : 0.f;
        float ai0 = (gi0 < nA) ? Ai[gi0] : 0.f;
        float ar1 = (gi1 < nA) ? Ar[gi1] : 0.f;
        float ai1 = (gi1 < nA) ? Ai[gi1] : 0.f;
        unsigned long long ab0 = pk2(ar0, ai0);
        unsigned long long ab1 = pk2(ar1, ai1);
#pragma unroll
        for (int r = 0; r < 16; r++) {
            ulonglong2 d2 = *(const ulonglong2*)&dxs2[r][k];
            acc[r] = ffma2(d2.x, ab0, acc[r]);
            acc[r] = ffma2(d2.y, ab1, acc[r]);
        }
    }
#pragma unroll
    for (int r = 0; r < 16; r++) {
        long long o = ((long long)((n0 + r) * 4 + c)) * 256 + tid;
        float re, im;
        upk2(acc[r], re, im);
        g_M[o] = make_float2(re, im);
    }
}

// ---------------------------------------------------------------------------
// complex 16x16 matmul, 4x4 per-thread tile: rows r0..r0+3, cols j0..j0+3.
// Dual packed accumulators: cr = P.lo - Q.hi, ci = P.hi + Q.lo.
// ---------------------------------------------------------------------------
__device__ __forceinline__ void mm16_44(const float2* __restrict__ A,
                                        const float2* __restrict__ B,
                                        float2 c[4][4], int rg68, int j0) {
    unsigned long long accP[4][4], accQ[4][4];
#pragma unroll
    for (int r = 0; r < 4; r++)
#pragma unroll
        for (int l = 0; l < 4; l++) { accP[r][l] = 0ULL; accQ[r][l] = 0ULL; }
#pragma unroll
    for (int k = 0; k < 16; k++) {
        unsigned long long ar[4], ai[4];
#pragma unroll
        for (int r = 0; r < 4; r++) {
            float2 a = A[rg68 + (r << 4) + k];
            ar[r] = pk2(a.x, a.x);
            ai[r] = pk2(a.y, a.y);
        }
        ulonglong2 b01 = *(const ulonglong2*)(B + EIDX(k, j0));
        ulonglong2 b23 = *(const ulonglong2*)(B + EIDX(k, j0) + 2);
#pragma unroll
        for (int r = 0; r < 4; r++) {
            accP[r][0] = ffma2(ar[r], b01.x, accP[r][0]);  accQ[r][0] = ffma2(ai[r], b01.x, accQ[r][0]);
            accP[r][1] = ffma2(ar[r], b01.y, accP[r][1]);  accQ[r][1] = ffma2(ai[r], b01.y, accQ[r][1]);
            accP[r][2] = ffma2(ar[r], b23.x, accP[r][2]);  accQ[r][2] = ffma2(ai[r], b23.x, accQ[r][2]);
            accP[r][3] = ffma2(ar[r], b23.y, accP[r][3]);  accQ[r][3] = ffma2(ai[r], b23.y, accQ[r][3]);
        }
    }
#pragma unroll
    for (int r = 0; r < 4; r++)
#pragma unroll
        for (int l = 0; l < 4; l++) {
            float pr, pi2, qr, qi;
            upk2(accP[r][l], pr, pi2);
            upk2(accQ[r][l], qr, qi);
            c[r][l] = make_float2(pr - qi, pi2 + qr);
        }
}

__device__ __forceinline__ void store44(float2* __restrict__ dst,
                                        const float2 c[4][4], int rg68, int j0) {
#pragma unroll
    for (int r = 0; r < 4; r++) {
        float4* p = (float4*)(dst + rg68 + (r << 4) + j0);
        p[0] = make_float4(c[r][0].x, c[r][0].y, c[r][1].x, c[r][1].y);
        p[1] = make_float4(c[r][2].x, c[r][2].y, c[r][3].x, c[r][3].y);
    }
}

// ---------------------------------------------------------------------------
// Kernel 2: expm of AX = 0.5*(M - M^H), degree-15 Taylor (PS) + squaring.
// HALF-WARP (16 lanes) PER MATRIX; 4 matrices per 64-thread block.
// Lane (within half): row group rg = l>>2 (rows 4rg..4rg+3), cols j0=(l&3)*4.
// Planes per matrix: Am, A2, A4, P (A3 lives in registers).
// ---------------------------------------------------------------------------
__global__ __launch_bounds__(64) void expm_kernel(float* __restrict__ out,
                                                  long long capF, int writeComplex) {
    __shared__ __align__(16) float2 sm[MPB * MST];

    int tid  = threadIdx.x;
    int mloc = tid >> 4;              // matrix slot in block: 0..3
    int l16  = tid & 15;
    int rg   = l16 >> 2;
    int r0   = rg << 2;
    int rg68 = rg * GST;
    int j0   = (l16 & 3) << 2;

    float2* Am = sm + mloc * MST;
    float2* A2 = Am + PL2;
    float2* A4 = Am + 2 * PL2;
    float2* Pp = Am + 3 * PL2;

    long long baseC = ((long long)blockIdx.x * MPB + mloc) * 256;

    // stage M tile (4 rows x 4 cols) into P plane
    {
#pragma unroll
        for (int r = 0; r < 4; r++) {
            const float4* g = (const float4*)(g_M + baseC + (r0 + r) * 16 + j0);
            float4 v0 = g[0], v1 = g[1];
            float4* p = (float4*)(Pp + rg68 + (r << 4) + j0);
            p[0] = v0; p[1] = v1;
        }
    }
    __syncwarp();

    // AX = 0.5*(M - M^H); per-column partial abs-sums
    float2 ax[4][4];
    float cs[4];
#pragma unroll
    for (int l = 0; l < 4; l++) cs[l] = 0.f;
#pragma unroll
    for (int r = 0; r < 4; r++) {
        int i = r0 + r;
#pragma unroll
        for (int l = 0; l < 4; l++) {
            int j = j0 + l;
            float2 mij = Pp[EIDX(i, j)];
            float2 mji = Pp[EIDX(j, i)];
            float xr = 0.5f * (mij.x - mji.x);
            float xi = 0.5f * (mij.y + mji.y);
            ax[r][l] = make_float2(xr, xi);
            cs[l] += sqrtf(xr * xr + xi * xi);
        }
    }
    // reduce column sums over the 4 row-groups (xor 4, 8 stays in half-warp)
#pragma unroll
    for (int off = 8; off >= 4; off >>= 1)
#pragma unroll
        for (int l = 0; l < 4; l++)
            cs[l] += __shfl_xor_sync(0xffffffffu, cs[l], off);
    float mx = fmaxf(fmaxf(cs[0], cs[1]), fmaxf(cs[2], cs[3]));
#pragma unroll
    for (int off = 2; off >= 1; off >>= 1)
        mx = fmaxf(mx, __shfl_xor_sync(0xffffffffu, mx, off));

    int s = 0;
    if (mx > 1.0f) s = (int)ceilf(log2f(mx));
    s -= 1;                     // theta = 2 for degree-15 Taylor: trunc ~ 3e-9
    if (s < 0) s = 0;
    if (s > 24) s = 24;
    float scale = exp2f(-(float)s);

    // scaled A
    {
        float2 c[4][4];
#pragma unroll
        for (int r = 0; r < 4; r++)
#pragma unroll
            for (int l = 0; l < 4; l++)
                c[r][l] = make_float2(ax[r][l].x * scale, ax[r][l].y * scale);
        store44(Am, c, rg68, j0);
    }
    __syncwarp();

    float2 a3[4][4];            // A3 tile in registers
    {
        float2 c[4][4];
        mm16_44(Am, Am, c, rg68, j0); store44(A2, c, rg68, j0);     // A2
        __syncwarp();
        mm16_44(A2, Am, a3, rg68, j0);                              // A3 -> regs
        mm16_44(A2, A2, c, rg68, j0); store44(A4, c, rg68, j0);     // A4
    }
    __syncwarp();

    const float c2  = 0.5f;
    const float c3  = 1.6666666666666666e-01f;
    const float c4  = 4.1666666666666664e-02f;
    const float c5  = 8.3333333333333332e-03f;
    const float c6  = 1.3888888888888889e-03f;
    const float c7  = 1.9841269841269841e-04f;
    const float c8  = 2.4801587301587302e-05f;
    const float c9  = 2.7557319223985893e-06f;
    const float c10 = 2.7557319223985888e-07f;
    const float c11 = 2.5052108385441720e-08f;
    const float c12 = 2.0876756987868100e-09f;
    const float c13 = 1.6059043836821613e-10f;
    const float c14 = 1.1470745597729725e-11f;
    const float c15 = 7.6471637318198164e-13f;

    // P = c12 I + c13 A + c14 A2 + c15 A3
#pragma unroll
    for (int r = 0; r < 4; r++) {
        int i = r0 + r;
#pragma unroll
        for (int l = 0; l < 4; l++) {
            int e = EIDX(i, j0 + l);
            float2 a = Am[e], b2 = A2[e];
            float2 v;
            v.x = c13 * a.x + c14 * b2.x + c15 * a3[r][l].x;
            v.y = c13 * a.y + c14 * b2.y + c15 * a3[r][l].y;
            if (i == j0 + l) v.x += c12;
            Pp[e] = v;
        }
    }
    __syncwarp();

    // Horner x3: P = P*A4 + (h0 I + h1 A + h2 A2 + h3 A3)
    // In-place, no syncs: all cross-lane reads precede stores in the single
    // warp instruction stream (no divergence here).
    const float h0[3] = { c8, c4, 1.0f };
    const float h1[3] = { c9, c5, 1.0f };
    const float h2[3] = { c10, c6, c2 };
    const float h3[3] = { c11, c7, c3 };
#pragma unroll
    for (int stp = 0; stp < 3; stp++) {
        float2 c[4][4];
        mm16_44(Pp, A4, c, rg68, j0);
#pragma unroll
        for (int r = 0; r < 4; r++) {
            int i = r0 + r;
#pragma unroll
            for (int l = 0; l < 4; l++) {
                int e = EIDX(i, j0 + l);
                float2 a = Am[e], b2 = A2[e];
                float2 v = c[r][l];
                v.x += h1[stp] * a.x + h2[stp] * b2.x + h3[stp] * a3[r][l].x;
                v.y += h1[stp] * a.y + h2[stp] * b2.y + h3[stp] * a3[r][l].y;
                if (i == j0 + l) v.x += h0[stp];
                Pp[e] = v;
            }
        }
    }
    __syncwarp();

    // repeated squaring: loop to warp-max s; store/swap predicated per matrix
    int sMax = s;
    sMax = max(sMax, __shfl_xor_sync(0xffffffffu, sMax, 16));
    float2* pr = Pp;
    float2* tr = Am;            // Am dead after Horner
    for (int it = 0; it < sMax; it++) {
        float2 c[4][4];
        mm16_44(pr, pr, c, rg68, j0);
        if (it < s) store44(tr, c, rg68, j0);
        __syncwarp();
        if (it < s) { float2* sw = pr; pr = tr; tr = sw; }
    }

    // write result (real-only float32 confirmed; complex path kept as fallback)
    if (writeComplex) {
#pragma unroll
        for (int r = 0; r < 4; r++) {
            int i = r0 + r;
#pragma unroll
            for (int l = 0; l < 4; l++) {
                int j = j0 + l;
                long long f = 2 * (baseC + i * 16 + j);
                float2 v = pr[EIDX(i, j)];
                if (f + 1 < capF) { out[f] = v.x; out[f + 1] = v.y; }
            }
        }
    } else {
#pragma unroll
        for (int r = 0; r < 4; r++) {
            int i = r0 + r;
            long long e = baseC + i * 16 + j0;
            if (e + 3 < capF) {
                float2 v0 = pr[EIDX(i, j0)],     v1 = pr[EIDX(i, j0 + 1)];
                float2 v2 = pr[EIDX(i, j0 + 2)], v3 = pr[EIDX(i, j0 + 3)];
                *(float4*)(out + e) = make_float4(v0.x, v1.x, v2.x, v3.x);
            }
        }
    }
}

// ---------------------------------------------------------------------------
extern "C" void kernel_launch(void* const* d_in, const int* in_sizes, int n_in,
                              void* d_out, int out_size) {
    int ix_dX = -1;
    for (int i = 0; i < n_in; i++)
        if (in_sizes[i] == (int)(NB * INK) || in_sizes[i] == (int)(NB * INK * 4)) { ix_dX = i; break; }
    if (ix_dX < 0) ix_dX = 0;
    int ia[2] = {0, 0}; int na = 0;
    for (int i = 0; i < n_in && na < 2; i++)
        if (i != ix_dX) ia[na++] = i;

    const float* dX = (const float*)d_in[ix_dX];
    const float* Ar = (const float*)d_in[ia[0]];
    const float* Ai = (const float*)d_in[ia[1]];
    float* outf = (float*)d_out;

    int nDX = in_sizes[ix_dX];
    int nA  = in_sizes[ia[0]] < in_sizes[ia[1]] ? in_sizes[ia[0]] : in_sizes[ia[1]];

    long long capF = (long long)out_size;
    if (capF > 2LL * TOTC) capF = 2LL * TOTC;
    int writeComplex = (capF >= 2LL * TOTC) ? 1 : 0;

    ax_kernel<<<(NB / 16) * CC, 256>>>(dX, Ar, Ai, nDX, nA);            // 4096 blocks
    expm_kernel<<<NB * CC / MPB, 64>>>(outf, capF, writeComplex);       // 16384 blocks
}